// round 1
// baseline (speedup 1.0000x reference)
#include <cuda_runtime.h>
#include <math.h>

#define B     64
#define NSUB  4
#define PP    128
#define TP    512
#define DD    256
#define HH    256
#define FEAT  131072
#define M1    128
#define NROWS (B*TP)            // 32768
#define KCHUNKS 128             // FEAT / 1024

// ---------------- scratch (device globals; no allocation) ----------------
__device__ float g_invn[B*TP];
__device__ float g_dinv[B*TP];
__device__ float g_A[(size_t)B*NSUB*PP*PP];        // 16.8 MB raw A blocks (diag=1)
__device__ float g_XW[(size_t)B*TP*HH];            // 33.5 MB
__device__ float g_Hb[(size_t)B*TP*HH];            // 33.5 MB
__device__ float g_sum[HH], g_sumsq[HH], g_scale[HH], g_shift[HH];
__device__ float g_Z1part[(size_t)KCHUNKS*B*M1];   // 4 MB split-K partials
__device__ float g_z1[B*M1];

// ---------------- 1/||x_row|| ----------------
__global__ void k_invn(const float* __restrict__ x) {
    int row  = blockIdx.x * 8 + (threadIdx.x >> 5);
    int lane = threadIdx.x & 31;
    const float* xr = x + (size_t)row * DD;
    float s = 0.f;
#pragma unroll
    for (int i = 0; i < 8; i++) { float v = xr[lane + 32*i]; s += v*v; }
#pragma unroll
    for (int o = 16; o; o >>= 1) s += __shfl_xor_sync(0xffffffffu, s, o);
    if (lane == 0) g_invn[row] = 1.0f / fmaxf(sqrtf(s), 1e-12f);
}

// ---------------- per-(b,n): A block = (cos+1)/2 * mask, diag=1; also dinv ----------------
__global__ void __launch_bounds__(256) k_simA(const float* __restrict__ x,
                                              const float* __restrict__ mask) {
    int bn = blockIdx.x;
    int b = bn >> 2, n = bn & 3;
    const float* Xb  = x + ((size_t)b*TP + n*PP) * DD;
    const float* inv = g_invn + b*TP + n*PP;
    __shared__ float sX[16][130];
    __shared__ float sdeg[PP];
    int tx = threadIdx.x & 15, ty = threadIdx.x >> 4;
    float acc[8][8];
#pragma unroll
    for (int i=0;i<8;i++)
#pragma unroll
        for (int j=0;j<8;j++) acc[i][j] = 0.f;

    for (int k0 = 0; k0 < DD; k0 += 16) {
        __syncthreads();
#pragma unroll
        for (int it = 0; it < 8; it++) {
            int idx = threadIdx.x + it*256;
            int r = idx >> 4, kk = idx & 15;
            sX[kk][r] = Xb[r*DD + k0 + kk];
        }
        __syncthreads();
#pragma unroll
        for (int kk = 0; kk < 16; kk++) {
            float a[8], bb[8];
#pragma unroll
            for (int i=0;i<8;i++) a[i]  = sX[kk][ty + 16*i];
#pragma unroll
            for (int j=0;j<8;j++) bb[j] = sX[kk][tx + 16*j];
#pragma unroll
            for (int i=0;i<8;i++)
#pragma unroll
                for (int j=0;j<8;j++) acc[i][j] = fmaf(a[i], bb[j], acc[i][j]);
        }
    }
    if (threadIdx.x < PP) sdeg[threadIdx.x] = 0.f;
    __syncthreads();

    float Ablk[8][8];
    float rsum[8];
#pragma unroll
    for (int i=0;i<8;i++) rsum[i] = 0.f;
#pragma unroll
    for (int i=0;i<8;i++) {
        int r = ty + 16*i;
        float ir = inv[r];
#pragma unroll
        for (int j=0;j<8;j++) {
            int c = tx + 16*j;
            float v = (acc[i][j] * ir * inv[c] + 1.0f) * 0.5f * mask[r*PP + c];
            if (r == c) v = 1.0f;        // edges diag zeroed, then +eye
            Ablk[i][j] = v;
            rsum[i] += v;
        }
    }
#pragma unroll
    for (int i=0;i<8;i++) atomicAdd(&sdeg[ty + 16*i], rsum[i]);
    __syncthreads();

    float* Ab = g_A + (size_t)bn * (PP*PP);
#pragma unroll
    for (int i=0;i<8;i++) {
        int r = ty + 16*i;
#pragma unroll
        for (int j=0;j<8;j++) Ab[r*PP + tx + 16*j] = Ablk[i][j];
    }
    if (threadIdx.x < PP) {
        float deg = sdeg[threadIdx.x];
        g_dinv[b*TP + n*PP + threadIdx.x] =
            (deg > 0.f) ? rsqrtf(fmaxf(deg, 1e-12f)) : 0.f;
    }
}

// ---------------- generic [32768,256] @ [256,256] + bias -> g_XW ----------------
__global__ void __launch_bounds__(256) k_xw(const float* __restrict__ A,
                                            const float* __restrict__ W,
                                            const float* __restrict__ bias) {
    __shared__ float sA[16][130];
    __shared__ float sB[16][130];
    int tx = threadIdx.x & 15, ty = threadIdx.x >> 4;
    int m0 = blockIdx.y * 128, n0 = blockIdx.x * 128;
    float acc[8][8];
#pragma unroll
    for (int i=0;i<8;i++)
#pragma unroll
        for (int j=0;j<8;j++) acc[i][j] = 0.f;

    for (int k0 = 0; k0 < 256; k0 += 16) {
        __syncthreads();
#pragma unroll
        for (int it = 0; it < 8; it++) {
            int idx = threadIdx.x + it*256;
            int r = idx >> 4, kk = idx & 15;
            sA[kk][r] = A[(size_t)(m0 + r)*256 + k0 + kk];
            int c = idx & 127, kk2 = idx >> 7;
            sB[kk2][c] = W[(k0 + kk2)*256 + n0 + c];
        }
        __syncthreads();
#pragma unroll
        for (int kk = 0; kk < 16; kk++) {
            float a[8], b[8];
#pragma unroll
            for (int i=0;i<8;i++) a[i] = sA[kk][ty + 16*i];
#pragma unroll
            for (int j=0;j<8;j++) b[j] = sB[kk][tx + 16*j];
#pragma unroll
            for (int i=0;i<8;i++)
#pragma unroll
                for (int j=0;j<8;j++) acc[i][j] = fmaf(a[i], b[j], acc[i][j]);
        }
    }
#pragma unroll
    for (int i=0;i<8;i++) {
        int r = m0 + ty + 16*i;
#pragma unroll
        for (int j=0;j<8;j++) {
            int c = n0 + tx + 16*j;
            g_XW[(size_t)r*256 + c] = acc[i][j] + bias[c];
        }
    }
}

// ---------------- H = dinv_i * A(b,n) @ (dinv_j * XW rows)  -> g_Hb ----------------
__global__ void __launch_bounds__(256) k_bmm() {
    int bn = blockIdx.y;
    int b = bn >> 2, n = bn & 3;
    int h0 = blockIdx.x * 128;
    const float* Ab    = g_A + (size_t)bn * (PP*PP);
    const float* dv    = g_dinv + b*TP + n*PP;
    const float* Xrows = g_XW + ((size_t)(b*TP + n*PP)) * HH;
    __shared__ float sA[16][130];
    __shared__ float sB[16][130];
    int tx = threadIdx.x & 15, ty = threadIdx.x >> 4;
    float acc[8][8];
#pragma unroll
    for (int i=0;i<8;i++)
#pragma unroll
        for (int j=0;j<8;j++) acc[i][j] = 0.f;

    for (int k0 = 0; k0 < PP; k0 += 16) {
        __syncthreads();
#pragma unroll
        for (int it = 0; it < 8; it++) {
            int idx = threadIdx.x + it*256;
            int r = idx >> 4, kk = idx & 15;
            sA[kk][r] = Ab[r*PP + k0 + kk];
            int c = idx & 127, kk2 = idx >> 7;
            sB[kk2][c] = Xrows[(size_t)(k0 + kk2)*HH + h0 + c] * dv[k0 + kk2];
        }
        __syncthreads();
#pragma unroll
        for (int kk = 0; kk < 16; kk++) {
            float a[8], b2[8];
#pragma unroll
            for (int i=0;i<8;i++) a[i]  = sA[kk][ty + 16*i];
#pragma unroll
            for (int j=0;j<8;j++) b2[j] = sB[kk][tx + 16*j];
#pragma unroll
            for (int i=0;i<8;i++)
#pragma unroll
                for (int j=0;j<8;j++) acc[i][j] = fmaf(a[i], b2[j], acc[i][j]);
        }
    }
    float* Hout = g_Hb + ((size_t)(b*TP + n*PP)) * HH;
#pragma unroll
    for (int i=0;i<8;i++) {
        int r = ty + 16*i;
        float dr = dv[r];
#pragma unroll
        for (int j=0;j<8;j++)
            Hout[(size_t)r*HH + h0 + tx + 16*j] = acc[i][j] * dr;
    }
}

// ---------------- BN helpers ----------------
__global__ void k_zero() { g_sum[threadIdx.x] = 0.f; g_sumsq[threadIdx.x] = 0.f; }

__global__ void k_stats() {
    int c = threadIdx.x;
    size_t row0 = (size_t)blockIdx.x * 256;
    float s = 0.f, s2 = 0.f;
    for (int r = 0; r < 256; r++) {
        float v = g_Hb[(row0 + r)*256 + c];
        s += v; s2 += v*v;
    }
    atomicAdd(&g_sum[c], s);
    atomicAdd(&g_sumsq[c], s2);
}

__global__ void k_bnfin(const float* __restrict__ g, const float* __restrict__ be) {
    int c = threadIdx.x;
    const float invn = 1.0f / (float)NROWS;
    float m = g_sum[c] * invn;
    float v = g_sumsq[c] * invn - m*m;
    float sc = g[c] * rsqrtf(v + 1e-5f);
    g_scale[c] = sc;
    g_shift[c] = be[c] - m*sc;
}

__global__ void k_bnrelu() {
    size_t i = (size_t)blockIdx.x * 256 + threadIdx.x;
    float4 v = reinterpret_cast<float4*>(g_Hb)[i];
    int c = (int)((i*4) & 255);
    v.x = fmaxf(fmaf(v.x, g_scale[c],   g_shift[c]),   0.f);
    v.y = fmaxf(fmaf(v.y, g_scale[c+1], g_shift[c+1]), 0.f);
    v.z = fmaxf(fmaf(v.z, g_scale[c+2], g_shift[c+2]), 0.f);
    v.w = fmaxf(fmaf(v.w, g_scale[c+3], g_shift[c+3]), 0.f);
    reinterpret_cast<float4*>(g_Hb)[i] = v;
}

// ---------------- split-K readout GEMM: [64,131072] @ [131072,128] ----------------
__global__ void __launch_bounds__(256) k_mlp1(const float* __restrict__ Wm1) {
    int kc = blockIdx.x;
    int k_base = kc * 1024;
    __shared__ float sG[16][66];
    __shared__ float sW[16][130];
    int tx = threadIdx.x & 31, ty = threadIdx.x >> 5;   // tx:0..31, ty:0..7
    float acc[8][4];
#pragma unroll
    for (int i=0;i<8;i++)
#pragma unroll
        for (int j=0;j<4;j++) acc[i][j] = 0.f;

    for (int k0 = 0; k0 < 1024; k0 += 16) {
        __syncthreads();
#pragma unroll
        for (int it = 0; it < 4; it++) {
            int idx = threadIdx.x + it*256;
            int bb = idx >> 4, kk = idx & 15;
            sG[kk][bb] = g_Hb[(size_t)bb*FEAT + k_base + k0 + kk];
        }
#pragma unroll
        for (int it = 0; it < 8; it++) {
            int idx = threadIdx.x + it*256;
            int m = idx & 127, kk = idx >> 7;
            sW[kk][m] = Wm1[(size_t)(k_base + k0 + kk)*128 + m];
        }
        __syncthreads();
#pragma unroll
        for (int kk = 0; kk < 16; kk++) {
            float a[8], w[4];
#pragma unroll
            for (int i=0;i<8;i++) a[i] = sG[kk][ty + 8*i];
#pragma unroll
            for (int j=0;j<4;j++) w[j] = sW[kk][tx + 32*j];
#pragma unroll
            for (int i=0;i<8;i++)
#pragma unroll
                for (int j=0;j<4;j++) acc[i][j] = fmaf(a[i], w[j], acc[i][j]);
        }
    }
    float* out = g_Z1part + (size_t)kc * (B*M1);
#pragma unroll
    for (int i=0;i<8;i++)
#pragma unroll
        for (int j=0;j<4;j++)
            out[(ty + 8*i)*M1 + tx + 32*j] = acc[i][j];
}

__global__ void k_red(const float* __restrict__ bm1) {
    int o = blockIdx.x*256 + threadIdx.x;   // 0..8191
    float s = bm1[o & 127];
    for (int kc = 0; kc < KCHUNKS; kc++) s += g_Z1part[(size_t)kc*(B*M1) + o];
    g_z1[o] = s;
}

// ---------------- head: bn1d+relu, z@Wm2, bn1d+relu, z@Wm3 ----------------
__global__ void __launch_bounds__(256) k_head(const float* __restrict__ gm1, const float* __restrict__ bem1,
                                              const float* __restrict__ Wm2, const float* __restrict__ bm2,
                                              const float* __restrict__ gm2, const float* __restrict__ bem2,
                                              const float* __restrict__ Wm3, const float* __restrict__ bm3,
                                              float* __restrict__ out) {
    __shared__ float sz1[64][128];   // 32 KB
    __shared__ float sz2[64][64];    // 16 KB
    int tid = threadIdx.x;

    if (tid < 128) {
        float s = 0.f, s2 = 0.f;
        for (int b = 0; b < 64; b++) { float v = g_z1[b*128 + tid]; s += v; s2 += v*v; }
        float m = s * (1.f/64.f), var = s2 * (1.f/64.f) - m*m;
        float sc = gm1[tid] * rsqrtf(var + 1e-5f);
        float sh = bem1[tid] - m*sc;
        for (int b = 0; b < 64; b++)
            sz1[b][tid] = fmaxf(fmaf(g_z1[b*128 + tid], sc, sh), 0.f);
    }
    __syncthreads();

    for (int o = tid; o < 4096; o += 256) {
        int b = o >> 6, j = o & 63;
        float s = bm2[j];
#pragma unroll 8
        for (int m = 0; m < 128; m++) s = fmaf(sz1[b][m], Wm2[m*64 + j], s);
        sz2[b][j] = s;
    }
    __syncthreads();

    if (tid < 64) {
        float s = 0.f, s2 = 0.f;
        for (int b = 0; b < 64; b++) { float v = sz2[b][tid]; s += v; s2 += v*v; }
        float m = s * (1.f/64.f), var = s2 * (1.f/64.f) - m*m;
        float sc = gm2[tid] * rsqrtf(var + 1e-5f);
        float sh = bem2[tid] - m*sc;
        for (int b = 0; b < 64; b++)
            sz2[b][tid] = fmaxf(fmaf(sz2[b][tid], sc, sh), 0.f);
    }
    __syncthreads();

    if (tid < 128) {
        int b = tid >> 1, c = tid & 1;
        float s = bm3[c];
#pragma unroll
        for (int j = 0; j < 64; j++) s = fmaf(sz2[b][j], Wm3[j*2 + c], s);
        out[b*2 + c] = s;
    }
}

// ---------------- launch ----------------
extern "C" void kernel_launch(void* const* d_in, const int* in_sizes, int n_in,
                              void* d_out, int out_size) {
    const float* x    = (const float*)d_in[0];
    const float* mask = (const float*)d_in[1];
    const float* W1   = (const float*)d_in[2];
    const float* b1   = (const float*)d_in[3];
    const float* g1   = (const float*)d_in[4];
    const float* be1  = (const float*)d_in[5];
    const float* W2   = (const float*)d_in[6];
    const float* b2   = (const float*)d_in[7];
    const float* g2   = (const float*)d_in[8];
    const float* be2  = (const float*)d_in[9];
    const float* Wm1  = (const float*)d_in[10];
    const float* bm1  = (const float*)d_in[11];
    const float* gm1  = (const float*)d_in[12];
    const float* bem1 = (const float*)d_in[13];
    const float* Wm2  = (const float*)d_in[14];
    const float* bm2  = (const float*)d_in[15];
    const float* gm2  = (const float*)d_in[16];
    const float* bem2 = (const float*)d_in[17];
    const float* Wm3  = (const float*)d_in[18];
    const float* bm3  = (const float*)d_in[19];
    float* out = (float*)d_out;

    static float* pHb = nullptr;
    if (!pHb) cudaGetSymbolAddress((void**)&pHb, g_Hb);

    // norms + adjacency blocks
    k_invn<<<NROWS/8, 256>>>(x);
    k_simA<<<B*NSUB, 256>>>(x, mask);

    // ---- GCN layer 1 ----
    k_xw<<<dim3(2, NROWS/128), 256>>>(x, W1, b1);
    k_bmm<<<dim3(2, B*NSUB), 256>>>();
    k_zero<<<1, 256>>>();
    k_stats<<<NROWS/256, 256>>>();
    k_bnfin<<<1, 256>>>(g1, be1);
    k_bnrelu<<<(B*TP*HH)/4/256, 256>>>();

    // ---- GCN layer 2 ----
    k_xw<<<dim3(2, NROWS/128), 256>>>(pHb, W2, b2);
    k_bmm<<<dim3(2, B*NSUB), 256>>>();
    k_zero<<<1, 256>>>();
    k_stats<<<NROWS/256, 256>>>();
    k_bnfin<<<1, 256>>>(g2, be2);
    k_bnrelu<<<(B*TP*HH)/4/256, 256>>>();

    // ---- readout + head ----
    k_mlp1<<<KCHUNKS, 256>>>(Wm1);
    k_red<<<32, 256>>>(bm1);
    k_head<<<1, 256>>>(gm1, bem1, Wm2, bm2, gm2, bem2, Wm3, bm3, out);
}

// round 2
// speedup vs baseline: 2.0631x; 2.0631x over previous
#include <cuda_runtime.h>
#include <math.h>
#include <stdint.h>

#define B     64
#define NSUB  4
#define PP    128
#define TP    512
#define DD    256
#define HH    256
#define FEAT  131072
#define M1    128
#define NROWS (B*TP)            // 32768
#define KCHUNKS 128             // FEAT / 1024

#define SA_STR 36               // 32 + 4 pad (float4-aligned, conflict-free frags)
#define SB_STR 132              // 128 + 4 pad

// ---------------- scratch (device globals; no allocation) ----------------
__device__ float g_invn[B*TP];
__device__ float g_dinv[B*TP];
__device__ float g_A[(size_t)B*NSUB*PP*PP];        // 16.8 MB raw A blocks (diag=1)
__device__ float g_XW[(size_t)B*TP*HH];            // 33.5 MB
__device__ float g_Hb[(size_t)B*TP*HH];            // 33.5 MB
__device__ float g_sum[HH], g_sumsq[HH], g_scale[HH], g_shift[HH];
__device__ float g_Z1part[(size_t)KCHUNKS*B*M1];   // 4 MB split-K partials
__device__ float g_z1[B*M1];

// ---------------- tf32 helpers ----------------
__device__ __forceinline__ float tf32r(float x) {
    uint32_t u;
    asm("cvt.rna.tf32.f32 %0, %1;" : "=r"(u) : "f"(x));
    return __uint_as_float(u);
}
__device__ __forceinline__ void mma8(float* c, const uint32_t* a, const uint32_t* b) {
    asm volatile("mma.sync.aligned.m16n8k8.row.col.f32.tf32.tf32.f32 "
                 "{%0,%1,%2,%3}, {%4,%5,%6,%7}, {%8,%9}, {%0,%1,%2,%3};\n"
                 : "+f"(c[0]), "+f"(c[1]), "+f"(c[2]), "+f"(c[3])
                 : "r"(a[0]), "r"(a[1]), "r"(a[2]), "r"(a[3]),
                   "r"(b[0]), "r"(b[1]));
}
#define F2U(x) __float_as_uint(x)

// ---------------- 1/||x_row|| (exact fp32) ----------------
__global__ void k_invn(const float* __restrict__ x) {
    int row  = blockIdx.x * 8 + (threadIdx.x >> 5);
    int lane = threadIdx.x & 31;
    const float* xr = x + (size_t)row * DD;
    float s = 0.f;
#pragma unroll
    for (int i = 0; i < 8; i++) { float v = xr[lane + 32*i]; s += v*v; }
#pragma unroll
    for (int o = 16; o; o >>= 1) s += __shfl_xor_sync(0xffffffffu, s, o);
    if (lane == 0) g_invn[row] = 1.0f / fmaxf(sqrtf(s), 1e-12f);
}

// ---------------- per-(b,n): A = (cos+1)/2 * mask, diag=1; dinv ----------------
__global__ void __launch_bounds__(256) k_simA(const float* __restrict__ x,
                                              const float* __restrict__ mask) {
    __shared__ float sX[128*SA_STR];
    __shared__ float sInv[128];
    __shared__ float sdeg[128];
    int bn = blockIdx.x;
    int b = bn >> 2, n = bn & 3;
    const float* Xb = x + ((size_t)b*TP + n*PP) * DD;
    int tid = threadIdx.x, w = tid >> 5, lane = tid & 31, g = lane >> 2, t = lane & 3;
    int wm = w & 3, wn = w >> 2;
    if (tid < 128) sInv[tid] = g_invn[b*TP + n*PP + tid];

    float acc[2][8][4];
#pragma unroll
    for (int mi=0;mi<2;mi++)
#pragma unroll
        for (int ni=0;ni<8;ni++)
#pragma unroll
            for (int q=0;q<4;q++) acc[mi][ni][q] = 0.f;

    for (int k0 = 0; k0 < DD; k0 += 32) {
        __syncthreads();
#pragma unroll
        for (int it = 0; it < 4; it++) {
            int idx = tid + it*256;
            int r = idx >> 3, q = (idx & 7) * 4;
            float4 v = *(const float4*)(Xb + (size_t)r*DD + k0 + q);
            sX[r*SA_STR+q+0] = tf32r(v.x); sX[r*SA_STR+q+1] = tf32r(v.y);
            sX[r*SA_STR+q+2] = tf32r(v.z); sX[r*SA_STR+q+3] = tf32r(v.w);
        }
        __syncthreads();
#pragma unroll
        for (int kk = 0; kk < 32; kk += 8) {
            uint32_t a[2][4], bf[8][2];
#pragma unroll
            for (int mi=0;mi<2;mi++) {
                int rb = wm*32 + mi*16;
                a[mi][0] = F2U(sX[(rb+g  )*SA_STR + kk+t  ]);
                a[mi][1] = F2U(sX[(rb+g+8)*SA_STR + kk+t  ]);
                a[mi][2] = F2U(sX[(rb+g  )*SA_STR + kk+t+4]);
                a[mi][3] = F2U(sX[(rb+g+8)*SA_STR + kk+t+4]);
            }
#pragma unroll
            for (int ni=0;ni<8;ni++) {
                int cb = wn*64 + ni*8 + g;
                bf[ni][0] = F2U(sX[cb*SA_STR + kk+t  ]);
                bf[ni][1] = F2U(sX[cb*SA_STR + kk+t+4]);
            }
#pragma unroll
            for (int mi=0;mi<2;mi++)
#pragma unroll
                for (int ni=0;ni<8;ni++) mma8(acc[mi][ni], a[mi], bf[ni]);
        }
    }
    __syncthreads();
    if (tid < 128) sdeg[tid] = 0.f;
    __syncthreads();

    float* Ab = g_A + (size_t)bn * (PP*PP);
    float rs[4] = {0.f, 0.f, 0.f, 0.f};
#pragma unroll
    for (int mi=0;mi<2;mi++) {
        int r0 = wm*32 + mi*16 + g, r1 = r0 + 8;
        float i0 = sInv[r0], i1 = sInv[r1];
#pragma unroll
        for (int ni=0;ni<8;ni++) {
            int c0 = wn*64 + ni*8 + 2*t, c1 = c0 + 1;
            float ic0 = sInv[c0], ic1 = sInv[c1];
            float v00 = (r0==c0) ? 1.f : (acc[mi][ni][0]*i0*ic0 + 1.f)*0.5f*mask[r0*PP+c0];
            float v01 = (r0==c1) ? 1.f : (acc[mi][ni][1]*i0*ic1 + 1.f)*0.5f*mask[r0*PP+c1];
            float v10 = (r1==c0) ? 1.f : (acc[mi][ni][2]*i1*ic0 + 1.f)*0.5f*mask[r1*PP+c0];
            float v11 = (r1==c1) ? 1.f : (acc[mi][ni][3]*i1*ic1 + 1.f)*0.5f*mask[r1*PP+c1];
            float2 s0 = make_float2(v00, v01);
            float2 s1 = make_float2(v10, v11);
            *(float2*)&Ab[r0*PP + c0] = s0;
            *(float2*)&Ab[r1*PP + c0] = s1;
            rs[mi*2+0] += v00 + v01;
            rs[mi*2+1] += v10 + v11;
        }
    }
#pragma unroll
    for (int mi=0;mi<2;mi++) {
        atomicAdd(&sdeg[wm*32 + mi*16 + g],     rs[mi*2+0]);
        atomicAdd(&sdeg[wm*32 + mi*16 + g + 8], rs[mi*2+1]);
    }
    __syncthreads();
    if (tid < 128) {
        float deg = sdeg[tid];
        g_dinv[b*TP + n*PP + tid] = (deg > 0.f) ? rsqrtf(fmaxf(deg, 1e-12f)) : 0.f;
    }
}

// ---------------- [32768,256] @ [256,256] + bias -> g_XW (tf32 mma) ----------------
__global__ void __launch_bounds__(256) k_xw(const float* __restrict__ A,
                                            const float* __restrict__ W,
                                            const float* __restrict__ bias) {
    __shared__ float sA[128*SA_STR];
    __shared__ float sB[32*SB_STR];
    int tid = threadIdx.x, w = tid >> 5, lane = tid & 31, g = lane >> 2, t = lane & 3;
    int wm = w & 3, wn = w >> 2;
    int m0 = blockIdx.y * 128, n0 = blockIdx.x * 128;
    float acc[2][8][4];
#pragma unroll
    for (int mi=0;mi<2;mi++)
#pragma unroll
        for (int ni=0;ni<8;ni++)
#pragma unroll
            for (int q=0;q<4;q++) acc[mi][ni][q] = 0.f;

    for (int k0 = 0; k0 < 256; k0 += 32) {
        __syncthreads();
#pragma unroll
        for (int it = 0; it < 4; it++) {
            int idx = tid + it*256;
            int r = idx >> 3, q = (idx & 7) * 4;
            float4 v = *(const float4*)(A + (size_t)(m0+r)*256 + k0 + q);
            sA[r*SA_STR+q+0] = tf32r(v.x); sA[r*SA_STR+q+1] = tf32r(v.y);
            sA[r*SA_STR+q+2] = tf32r(v.z); sA[r*SA_STR+q+3] = tf32r(v.w);
        }
#pragma unroll
        for (int it = 0; it < 4; it++) {
            int idx = tid + it*256;
            int r = idx >> 5, q = (idx & 31) * 4;
            float4 v = *(const float4*)(W + (size_t)(k0+r)*256 + n0 + q);
            sB[r*SB_STR+q+0] = tf32r(v.x); sB[r*SB_STR+q+1] = tf32r(v.y);
            sB[r*SB_STR+q+2] = tf32r(v.z); sB[r*SB_STR+q+3] = tf32r(v.w);
        }
        __syncthreads();
#pragma unroll
        for (int kk = 0; kk < 32; kk += 8) {
            uint32_t a[2][4], bf[8][2];
#pragma unroll
            for (int mi=0;mi<2;mi++) {
                int rb = wm*32 + mi*16;
                a[mi][0] = F2U(sA[(rb+g  )*SA_STR + kk+t  ]);
                a[mi][1] = F2U(sA[(rb+g+8)*SA_STR + kk+t  ]);
                a[mi][2] = F2U(sA[(rb+g  )*SA_STR + kk+t+4]);
                a[mi][3] = F2U(sA[(rb+g+8)*SA_STR + kk+t+4]);
            }
#pragma unroll
            for (int ni=0;ni<8;ni++) {
                int cb = wn*64 + ni*8 + g;
                bf[ni][0] = F2U(sB[(kk+t  )*SB_STR + cb]);
                bf[ni][1] = F2U(sB[(kk+t+4)*SB_STR + cb]);
            }
#pragma unroll
            for (int mi=0;mi<2;mi++)
#pragma unroll
                for (int ni=0;ni<8;ni++) mma8(acc[mi][ni], a[mi], bf[ni]);
        }
    }
#pragma unroll
    for (int mi=0;mi<2;mi++) {
        int r0 = m0 + wm*32 + mi*16 + g, r1 = r0 + 8;
#pragma unroll
        for (int ni=0;ni<8;ni++) {
            int c0 = n0 + wn*64 + ni*8 + 2*t;
            float b0 = bias[c0], b1 = bias[c0+1];
            float2 s0 = make_float2(acc[mi][ni][0] + b0, acc[mi][ni][1] + b1);
            float2 s1 = make_float2(acc[mi][ni][2] + b0, acc[mi][ni][3] + b1);
            *(float2*)&g_XW[(size_t)r0*256 + c0] = s0;
            *(float2*)&g_XW[(size_t)r1*256 + c0] = s1;
        }
    }
}

// ---------------- H = dinv_i * A(b,n) @ (dinv_j * XW)  (tf32 mma) ----------------
__global__ void __launch_bounds__(256) k_bmm() {
    __shared__ float sA[128*SA_STR];
    __shared__ float sB[32*SB_STR];
    __shared__ float sDv[128];
    int bn = blockIdx.y;
    int b = bn >> 2, n = bn & 3;
    int h0 = blockIdx.x * 128;
    const float* Ab    = g_A + (size_t)bn * (PP*PP);
    const float* Xrows = g_XW + ((size_t)(b*TP + n*PP)) * HH;
    int tid = threadIdx.x, w = tid >> 5, lane = tid & 31, g = lane >> 2, t = lane & 3;
    int wm = w & 3, wn = w >> 2;
    if (tid < 128) sDv[tid] = g_dinv[b*TP + n*PP + tid];

    float acc[2][8][4];
#pragma unroll
    for (int mi=0;mi<2;mi++)
#pragma unroll
        for (int ni=0;ni<8;ni++)
#pragma unroll
            for (int q=0;q<4;q++) acc[mi][ni][q] = 0.f;

    for (int k0 = 0; k0 < PP; k0 += 32) {
        __syncthreads();
#pragma unroll
        for (int it = 0; it < 4; it++) {
            int idx = tid + it*256;
            int r = idx >> 3, q = (idx & 7) * 4;
            float4 v = *(const float4*)(Ab + (size_t)r*PP + k0 + q);
            sA[r*SA_STR+q+0] = tf32r(v.x); sA[r*SA_STR+q+1] = tf32r(v.y);
            sA[r*SA_STR+q+2] = tf32r(v.z); sA[r*SA_STR+q+3] = tf32r(v.w);
        }
#pragma unroll
        for (int it = 0; it < 4; it++) {
            int idx = tid + it*256;
            int r = idx >> 5, q = (idx & 31) * 4;
            float dv = sDv[k0+r];
            float4 v = *(const float4*)(Xrows + (size_t)(k0+r)*HH + h0 + q);
            sB[r*SB_STR+q+0] = tf32r(v.x*dv); sB[r*SB_STR+q+1] = tf32r(v.y*dv);
            sB[r*SB_STR+q+2] = tf32r(v.z*dv); sB[r*SB_STR+q+3] = tf32r(v.w*dv);
        }
        __syncthreads();
#pragma unroll
        for (int kk = 0; kk < 32; kk += 8) {
            uint32_t a[2][4], bf[8][2];
#pragma unroll
            for (int mi=0;mi<2;mi++) {
                int rb = wm*32 + mi*16;
                a[mi][0] = F2U(sA[(rb+g  )*SA_STR + kk+t  ]);
                a[mi][1] = F2U(sA[(rb+g+8)*SA_STR + kk+t  ]);
                a[mi][2] = F2U(sA[(rb+g  )*SA_STR + kk+t+4]);
                a[mi][3] = F2U(sA[(rb+g+8)*SA_STR + kk+t+4]);
            }
#pragma unroll
            for (int ni=0;ni<8;ni++) {
                int cb = wn*64 + ni*8 + g;
                bf[ni][0] = F2U(sB[(kk+t  )*SB_STR + cb]);
                bf[ni][1] = F2U(sB[(kk+t+4)*SB_STR + cb]);
            }
#pragma unroll
            for (int mi=0;mi<2;mi++)
#pragma unroll
                for (int ni=0;ni<8;ni++) mma8(acc[mi][ni], a[mi], bf[ni]);
        }
    }
    float* Hout = g_Hb + ((size_t)(b*TP + n*PP)) * HH;
#pragma unroll
    for (int mi=0;mi<2;mi++) {
        int r0 = wm*32 + mi*16 + g, r1 = r0 + 8;
        float d0 = sDv[r0], d1 = sDv[r1];
#pragma unroll
        for (int ni=0;ni<8;ni++) {
            int c0 = h0 + wn*64 + ni*8 + 2*t;
            float2 s0 = make_float2(acc[mi][ni][0]*d0, acc[mi][ni][1]*d0);
            float2 s1 = make_float2(acc[mi][ni][2]*d1, acc[mi][ni][3]*d1);
            *(float2*)&g_Hb[((size_t)(b*TP + n*PP) + r0)*HH + c0] = s0;
            *(float2*)&g_Hb[((size_t)(b*TP + n*PP) + r1)*HH + c0] = s1;
        }
    }
    (void)Hout;
}

// ---------------- BN helpers ----------------
__global__ void k_zero() { g_sum[threadIdx.x] = 0.f; g_sumsq[threadIdx.x] = 0.f; }

__global__ void k_stats() {
    int c = threadIdx.x;
    size_t row0 = (size_t)blockIdx.x * 256;
    float s = 0.f, s2 = 0.f;
    for (int r = 0; r < 256; r++) {
        float v = g_Hb[(row0 + r)*256 + c];
        s += v; s2 += v*v;
    }
    atomicAdd(&g_sum[c], s);
    atomicAdd(&g_sumsq[c], s2);
}

__global__ void k_bnfin(const float* __restrict__ g, const float* __restrict__ be) {
    int c = threadIdx.x;
    const float invn = 1.0f / (float)NROWS;
    float m = g_sum[c] * invn;
    float v = g_sumsq[c] * invn - m*m;
    float sc = g[c] * rsqrtf(v + 1e-5f);
    g_scale[c] = sc;
    g_shift[c] = be[c] - m*sc;
}

__global__ void k_bnrelu() {
    size_t i = (size_t)blockIdx.x * 256 + threadIdx.x;
    float4 v = reinterpret_cast<float4*>(g_Hb)[i];
    int c = (int)((i*4) & 255);
    v.x = fmaxf(fmaf(v.x, g_scale[c],   g_shift[c]),   0.f);
    v.y = fmaxf(fmaf(v.y, g_scale[c+1], g_shift[c+1]), 0.f);
    v.z = fmaxf(fmaf(v.z, g_scale[c+2], g_shift[c+2]), 0.f);
    v.w = fmaxf(fmaf(v.w, g_scale[c+3], g_shift[c+3]), 0.f);
    reinterpret_cast<float4*>(g_Hb)[i] = v;
}

// ---------------- split-K readout GEMM (tf32 mma): [64,131072] @ [131072,128] ----------------
__global__ void __launch_bounds__(256) k_mlp1(const float* __restrict__ Wm1) {
    __shared__ float sG[64*SA_STR];
    __shared__ float sW[32*SB_STR];
    int kc = blockIdx.x;
    int kbase = kc * 1024;
    int tid = threadIdx.x, w = tid >> 5, lane = tid & 31, g = lane >> 2, t = lane & 3;
    int wm = w & 3, wn = w >> 2;
    float acc[8][4];
#pragma unroll
    for (int ni=0;ni<8;ni++)
#pragma unroll
        for (int q=0;q<4;q++) acc[ni][q] = 0.f;

    for (int k0 = 0; k0 < 1024; k0 += 32) {
        __syncthreads();
#pragma unroll
        for (int it = 0; it < 2; it++) {
            int idx = tid + it*256;
            int r = idx >> 3, q = (idx & 7) * 4;
            float4 v = *(const float4*)(g_Hb + (size_t)r*FEAT + kbase + k0 + q);
            sG[r*SA_STR+q+0] = tf32r(v.x); sG[r*SA_STR+q+1] = tf32r(v.y);
            sG[r*SA_STR+q+2] = tf32r(v.z); sG[r*SA_STR+q+3] = tf32r(v.w);
        }
#pragma unroll
        for (int it = 0; it < 4; it++) {
            int idx = tid + it*256;
            int r = idx >> 5, q = (idx & 31) * 4;
            float4 v = *(const float4*)(Wm1 + (size_t)(kbase + k0 + r)*128 + q);
            sW[r*SB_STR+q+0] = tf32r(v.x); sW[r*SB_STR+q+1] = tf32r(v.y);
            sW[r*SB_STR+q+2] = tf32r(v.z); sW[r*SB_STR+q+3] = tf32r(v.w);
        }
        __syncthreads();
#pragma unroll
        for (int kk = 0; kk < 32; kk += 8) {
            uint32_t a[4], bf[8][2];
            int rb = wm*16;
            a[0] = F2U(sG[(rb+g  )*SA_STR + kk+t  ]);
            a[1] = F2U(sG[(rb+g+8)*SA_STR + kk+t  ]);
            a[2] = F2U(sG[(rb+g  )*SA_STR + kk+t+4]);
            a[3] = F2U(sG[(rb+g+8)*SA_STR + kk+t+4]);
#pragma unroll
            for (int ni=0;ni<8;ni++) {
                int cb = wn*64 + ni*8 + g;
                bf[ni][0] = F2U(sW[(kk+t  )*SB_STR + cb]);
                bf[ni][1] = F2U(sW[(kk+t+4)*SB_STR + cb]);
            }
#pragma unroll
            for (int ni=0;ni<8;ni++) mma8(acc[ni], a, bf[ni]);
        }
    }
    float* out = g_Z1part + (size_t)kc * (B*M1);
    int r0 = wm*16 + g, r1 = r0 + 8;
#pragma unroll
    for (int ni=0;ni<8;ni++) {
        int c0 = wn*64 + ni*8 + 2*t;
        float2 s0 = make_float2(acc[ni][0], acc[ni][1]);
        float2 s1 = make_float2(acc[ni][2], acc[ni][3]);
        *(float2*)&out[r0*M1 + c0] = s0;
        *(float2*)&out[r1*M1 + c0] = s1;
    }
}

__global__ void k_red(const float* __restrict__ bm1) {
    int o = blockIdx.x*256 + threadIdx.x;   // 0..8191
    float s = bm1[o & 127];
    for (int kc = 0; kc < KCHUNKS; kc++) s += g_Z1part[(size_t)kc*(B*M1) + o];
    g_z1[o] = s;
}

// ---------------- head: bn1d+relu, z@Wm2, bn1d+relu, z@Wm3 ----------------
__global__ void __launch_bounds__(256) k_head(const float* __restrict__ gm1, const float* __restrict__ bem1,
                                              const float* __restrict__ Wm2, const float* __restrict__ bm2,
                                              const float* __restrict__ gm2, const float* __restrict__ bem2,
                                              const float* __restrict__ Wm3, const float* __restrict__ bm3,
                                              float* __restrict__ out) {
    __shared__ float sz1[64][128];   // 32 KB
    __shared__ float sz2[64][64];    // 16 KB
    int tid = threadIdx.x;

    if (tid < 128) {
        float s = 0.f, s2 = 0.f;
        for (int b = 0; b < 64; b++) { float v = g_z1[b*128 + tid]; s += v; s2 += v*v; }
        float m = s * (1.f/64.f), var = s2 * (1.f/64.f) - m*m;
        float sc = gm1[tid] * rsqrtf(var + 1e-5f);
        float sh = bem1[tid] - m*sc;
        for (int b = 0; b < 64; b++)
            sz1[b][tid] = fmaxf(fmaf(g_z1[b*128 + tid], sc, sh), 0.f);
    }
    __syncthreads();

    for (int o = tid; o < 4096; o += 256) {
        int b = o >> 6, j = o & 63;
        float s = bm2[j];
#pragma unroll 8
        for (int m = 0; m < 128; m++) s = fmaf(sz1[b][m], Wm2[m*64 + j], s);
        sz2[b][j] = s;
    }
    __syncthreads();

    if (tid < 64) {
        float s = 0.f, s2 = 0.f;
        for (int b = 0; b < 64; b++) { float v = sz2[b][tid]; s += v; s2 += v*v; }
        float m = s * (1.f/64.f), var = s2 * (1.f/64.f) - m*m;
        float sc = gm2[tid] * rsqrtf(var + 1e-5f);
        float sh = bem2[tid] - m*sc;
        for (int b = 0; b < 64; b++)
            sz2[b][tid] = fmaxf(fmaf(sz2[b][tid], sc, sh), 0.f);
    }
    __syncthreads();

    if (tid < 128) {
        int b = tid >> 1, c = tid & 1;
        float s = bm3[c];
#pragma unroll
        for (int j = 0; j < 64; j++) s = fmaf(sz2[b][j], Wm3[j*2 + c], s);
        out[b*2 + c] = s;
    }
}

// ---------------- launch ----------------
extern "C" void kernel_launch(void* const* d_in, const int* in_sizes, int n_in,
                              void* d_out, int out_size) {
    const float* x    = (const float*)d_in[0];
    const float* mask = (const float*)d_in[1];
    const float* W1   = (const float*)d_in[2];
    const float* b1   = (const float*)d_in[3];
    const float* g1   = (const float*)d_in[4];
    const float* be1  = (const float*)d_in[5];
    const float* W2   = (const float*)d_in[6];
    const float* b2   = (const float*)d_in[7];
    const float* g2   = (const float*)d_in[8];
    const float* be2  = (const float*)d_in[9];
    const float* Wm1  = (const float*)d_in[10];
    const float* bm1  = (const float*)d_in[11];
    const float* gm1  = (const float*)d_in[12];
    const float* bem1 = (const float*)d_in[13];
    const float* Wm2  = (const float*)d_in[14];
    const float* bm2  = (const float*)d_in[15];
    const float* gm2  = (const float*)d_in[16];
    const float* bem2 = (const float*)d_in[17];
    const float* Wm3  = (const float*)d_in[18];
    const float* bm3  = (const float*)d_in[19];
    float* out = (float*)d_out;

    static float* pHb = nullptr;
    if (!pHb) cudaGetSymbolAddress((void**)&pHb, g_Hb);

    // norms + adjacency blocks
    k_invn<<<NROWS/8, 256>>>(x);
    k_simA<<<B*NSUB, 256>>>(x, mask);

    // ---- GCN layer 1 ----
    k_xw<<<dim3(2, NROWS/128), 256>>>(x, W1, b1);
    k_bmm<<<dim3(2, B*NSUB), 256>>>();
    k_zero<<<1, 256>>>();
    k_stats<<<NROWS/256, 256>>>();
    k_bnfin<<<1, 256>>>(g1, be1);
    k_bnrelu<<<(B*TP*HH)/4/256, 256>>>();

    // ---- GCN layer 2 ----
    k_xw<<<dim3(2, NROWS/128), 256>>>(pHb, W2, b2);
    k_bmm<<<dim3(2, B*NSUB), 256>>>();
    k_zero<<<1, 256>>>();
    k_stats<<<NROWS/256, 256>>>();
    k_bnfin<<<1, 256>>>(g2, be2);
    k_bnrelu<<<(B*TP*HH)/4/256, 256>>>();

    // ---- readout + head ----
    k_mlp1<<<KCHUNKS, 256>>>(Wm1);
    k_red<<<32, 256>>>(bm1);
    k_head<<<1, 256>>>(gm1, bem1, Wm2, bm2, gm2, bem2, Wm3, bm3, out);
}